// round 5
// baseline (speedup 1.0000x reference)
#include <cuda_runtime.h>
#include <math.h>

#define NTOK 1024   // B*S = 2*512

// Scratch (device globals)
__device__ float g_A[3 * 64 * 512];         // folded Pin@W_head
__device__ float g_U[512 * 64];             // folded Wo@Pout_v
__device__ float g_qp_part[4 * NTOK * 192]; // split-K partials of x@A^T
__device__ float g_Y[NTOK * 64];            // attn out (normalized), [n][h*8+q]

// ---------------------------------------------------------------------------
// Fold kernel. Blocks 0..47: A = Pin@W_head. Blocks 48..63: U = Wo@Pout_v.
// ---------------------------------------------------------------------------
__global__ __launch_bounds__(256) void k_fold(
    const float* __restrict__ Wq, const float* __restrict__ Wk,
    const float* __restrict__ Wv, const float* __restrict__ Wo,
    const float* __restrict__ Pq, const float* __restrict__ Pk,
    const float* __restrict__ Pv, const float* __restrict__ Pov) {
    __shared__ float sP[512];
    int blk = blockIdx.x;
    int t = threadIdx.x;
    if (blk < 48) {
        int idx = blk * 256 + t;
        int stream = idx >> 12;
        int rem = idx & 4095;
        int h = rem >> 9;
        int e = rem & 511;
        const float* W = (stream == 0) ? Wq : ((stream == 1) ? Wk : Wv);
        const float* P = (stream == 0) ? Pq : ((stream == 1) ? Pk : Pv);
        sP[t] = P[t];
        sP[t + 256] = P[t + 256];
        __syncthreads();
        float acc[8] = {};
#pragma unroll
        for (int d = 0; d < 64; ++d) {
            float w = W[(h * 64 + d) * 512 + e];
#pragma unroll
            for (int q = 0; q < 8; ++q)
                acc[q] = fmaf(sP[q * 64 + d], w, acc[q]);
        }
#pragma unroll
        for (int q = 0; q < 8; ++q)
            g_A[(stream * 64 + h * 8 + q) * 512 + e] = acc[q];
    } else {
        int idx = (blk - 48) * 256 + t;
        sP[t] = Pov[t];
        sP[t + 256] = Pov[t + 256];
        __syncthreads();
        int e = idx >> 3, h = idx & 7;
        float acc[8] = {};
#pragma unroll
        for (int d = 0; d < 64; ++d) {
            float w = Wo[e * 512 + h * 64 + d];
#pragma unroll
            for (int q = 0; q < 8; ++q)
                acc[q] = fmaf(w, sP[d * 8 + q], acc[q]);
        }
#pragma unroll
        for (int q = 0; q < 8; ++q)
            g_U[e * 64 + h * 8 + q] = acc[q];
    }
}

// ---------------------------------------------------------------------------
// Split-K GEMM: qp_part[z] = x[:, z*128:(z+1)*128] @ A[:, same]^T
// grid (3, 16, 4), 128 threads, 64x64 tile, BK=32, 8x4 microtile (FMA-bound)
// ---------------------------------------------------------------------------
__global__ __launch_bounds__(128) void k_gemm_qp(const float* __restrict__ A) {
    const float* B = g_A;
    __shared__ float As[32][64];
    __shared__ float Bs[32][64];
    int bm = blockIdx.y * 64, bn = blockIdx.x * 64;
    int z = blockIdx.z;
    float* C = g_qp_part + z * (NTOK * 192);
    int tid = threadIdx.x;
    int tx = tid & 15;       // 16 col groups of 4
    int ty = tid >> 4;       // 8 row groups of 8
    float acc[8][4] = {};
    for (int kk = z * 128; kk < z * 128 + 128; kk += 32) {
#pragma unroll
        for (int i = 0; i < 4; ++i) {
            int t = tid + i * 128;            // 0..511
            int row = t >> 3;                 // 0..63
            int c4 = (t & 7) * 4;             // 0..28
            float4 va = *(const float4*)(A + (size_t)(bm + row) * 512 + kk + c4);
            As[c4 + 0][row] = va.x; As[c4 + 1][row] = va.y;
            As[c4 + 2][row] = va.z; As[c4 + 3][row] = va.w;
            float4 vb = *(const float4*)(B + (size_t)(bn + row) * 512 + kk + c4);
            Bs[c4 + 0][row] = vb.x; Bs[c4 + 1][row] = vb.y;
            Bs[c4 + 2][row] = vb.z; Bs[c4 + 3][row] = vb.w;
        }
        __syncthreads();
#pragma unroll 8
        for (int k = 0; k < 32; ++k) {
            float4 a0 = *(const float4*)&As[k][ty * 8];
            float4 a1 = *(const float4*)&As[k][ty * 8 + 4];
            float4 b = *(const float4*)&Bs[k][tx * 4];
            float av[8] = {a0.x, a0.y, a0.z, a0.w, a1.x, a1.y, a1.z, a1.w};
            float bv[4] = {b.x, b.y, b.z, b.w};
#pragma unroll
            for (int i = 0; i < 8; ++i)
#pragma unroll
                for (int j = 0; j < 4; ++j)
                    acc[i][j] = fmaf(av[i], bv[j], acc[i][j]);
        }
        __syncthreads();
    }
#pragma unroll
    for (int i = 0; i < 8; ++i) {
        float4 o = make_float4(acc[i][0], acc[i][1], acc[i][2], acc[i][3]);
        *(float4*)(C + (size_t)(bm + ty * 8 + i) * 192 + bn + tx * 4) = o;
    }
}

// ---------------------------------------------------------------------------
// Fused z + rank-8 attention. grid (8 qtiles, 16 bh), 512 threads.
// Prologue: M = Pout_q^T Pout_k / 8, ct = cos(theta_w + theta_{8+w}); then
// z for all 512 keys (k & v streams) + 64 q rows from split-K partials.
// Main: thread = (row 0..63, sub 0..7), 64 keys each, single-pass softmax
// (scores provably bounded, no max needed), shfl reduction over subs.
// smem rows stride 12 -> LDS.128, conflict-free.
// ---------------------------------------------------------------------------
__global__ __launch_bounds__(512) void k_attn4(const float* __restrict__ Poq,
                                               const float* __restrict__ Pok,
                                               const float* __restrict__ theta) {
    extern __shared__ float sm[];
    float* s_zk = sm;                  // 512*12
    float* s_zv = sm + 512 * 12;       // 512*12
    float* s_zq = sm + 1024 * 12;      // 64*12
    float* sM   = sm + 1024 * 12 + 64 * 12;  // 64
    float* sct  = sM + 64;             // 8

    int bh = blockIdx.y;
    int b = bh >> 3, h = bh & 7;
    int q0 = blockIdx.x * 64;
    int tid = threadIdx.x;

    // Phase A: M and ct
    if (tid < 64) {
        int i = tid >> 3, j = tid & 7;
        float acc = 0.f;
#pragma unroll
        for (int d = 0; d < 64; ++d)
            acc = fmaf(Poq[d * 8 + i], Pok[d * 8 + j], acc);
        sM[tid] = acc * 0.125f;
    } else if (tid < 72) {
        int w = tid - 64;
        sct[w] = cosf(theta[w] + theta[8 + w]);
    }
    __syncthreads();

    // Phase B: compute z rows. Tasks: 0..63 zq, 64..575 zk, 576..1087 zv.
#pragma unroll
    for (int task = tid; task < 1088; task += 512) {
        int stream, s, n;
        float* dst;
        if (task < 64) {
            stream = 0; s = q0 + task; dst = s_zq + task * 12;
        } else if (task < 576) {
            stream = 1; s = task - 64; dst = s_zk + (task - 64) * 12;
        } else {
            stream = 2; s = task - 576; dst = s_zv + (task - 576) * 12;
        }
        n = b * 512 + s;
        int base = n * 192 + stream * 64 + h * 8;
        float4 a0 = *(const float4*)(g_qp_part + base);
        float4 a1 = *(const float4*)(g_qp_part + base + 4);
        float4 b0 = *(const float4*)(g_qp_part + NTOK * 192 + base);
        float4 b1 = *(const float4*)(g_qp_part + NTOK * 192 + base + 4);
        float4 c0 = *(const float4*)(g_qp_part + 2 * NTOK * 192 + base);
        float4 c1 = *(const float4*)(g_qp_part + 2 * NTOK * 192 + base + 4);
        float4 d0 = *(const float4*)(g_qp_part + 3 * NTOK * 192 + base);
        float4 d1 = *(const float4*)(g_qp_part + 3 * NTOK * 192 + base + 4);
        float ang[8];
        ang[0] = a0.x + b0.x + c0.x + d0.x;
        ang[1] = a0.y + b0.y + c0.y + d0.y;
        ang[2] = a0.z + b0.z + c0.z + d0.z;
        ang[3] = a0.w + b0.w + c0.w + d0.w;
        ang[4] = a1.x + b1.x + c1.x + d1.x;
        ang[5] = a1.y + b1.y + c1.y + d1.y;
        ang[6] = a1.z + b1.z + c1.z + d1.z;
        ang[7] = a1.w + b1.w + c1.w + d1.w;
        float z[8];
        float p = 1.f;
#pragma unroll
        for (int w = 0; w < 8; ++w) {
            p *= cosf(ang[w]) * sct[w];
            z[w] = p;
        }
        if (stream == 0) {
            float y[8];
#pragma unroll
            for (int j = 0; j < 8; ++j) {
                float acc = 0.f;
#pragma unroll
                for (int i = 0; i < 8; ++i)
                    acc = fmaf(z[i], sM[i * 8 + j], acc);
                y[j] = acc;
            }
            *(float4*)dst = make_float4(y[0], y[1], y[2], y[3]);
            *(float4*)(dst + 4) = make_float4(y[4], y[5], y[6], y[7]);
        } else {
            *(float4*)dst = make_float4(z[0], z[1], z[2], z[3]);
            *(float4*)(dst + 4) = make_float4(z[4], z[5], z[6], z[7]);
        }
    }
    __syncthreads();

    // Main loop: one q row per thread, 1/8 of keys per sub.
    int row = tid >> 3, sub = tid & 7;
    float y[8];
    {
        float4 a = *(const float4*)(s_zq + row * 12);
        float4 bq = *(const float4*)(s_zq + row * 12 + 4);
        y[0] = a.x; y[1] = a.y; y[2] = a.z; y[3] = a.w;
        y[4] = bq.x; y[5] = bq.y; y[6] = bq.z; y[7] = bq.w;
    }
    float l = 0.f;
    float acc[8] = {};
#pragma unroll 4
    for (int it = 0; it < 64; ++it) {
        int key = sub + it * 8;
        float4 k0 = *(const float4*)(s_zk + key * 12);
        float4 k1 = *(const float4*)(s_zk + key * 12 + 4);
        float s = y[0] * k0.x;
        s = fmaf(y[1], k0.y, s);
        s = fmaf(y[2], k0.z, s);
        s = fmaf(y[3], k0.w, s);
        s = fmaf(y[4], k1.x, s);
        s = fmaf(y[5], k1.y, s);
        s = fmaf(y[6], k1.z, s);
        s = fmaf(y[7], k1.w, s);
        float p = __expf(s);
        l += p;
        float4 v0 = *(const float4*)(s_zv + key * 12);
        float4 v1 = *(const float4*)(s_zv + key * 12 + 4);
        acc[0] = fmaf(p, v0.x, acc[0]);
        acc[1] = fmaf(p, v0.y, acc[1]);
        acc[2] = fmaf(p, v0.z, acc[2]);
        acc[3] = fmaf(p, v0.w, acc[3]);
        acc[4] = fmaf(p, v1.x, acc[4]);
        acc[5] = fmaf(p, v1.y, acc[5]);
        acc[6] = fmaf(p, v1.z, acc[6]);
        acc[7] = fmaf(p, v1.w, acc[7]);
    }
#pragma unroll
    for (int d = 1; d <= 4; d <<= 1) {
        l += __shfl_xor_sync(0xffffffffu, l, d);
#pragma unroll
        for (int j = 0; j < 8; ++j)
            acc[j] += __shfl_xor_sync(0xffffffffu, acc[j], d);
    }
    if (sub == 0) {
        float inv = 1.f / l;
        int n0 = b * 512 + q0 + row;
        float4* o = (float4*)(g_Y + (size_t)n0 * 64 + h * 8);
        o[0] = make_float4(acc[0] * inv, acc[1] * inv, acc[2] * inv, acc[3] * inv);
        o[1] = make_float4(acc[4] * inv, acc[5] * inv, acc[6] * inv, acc[7] * inv);
    }
}

// ---------------------------------------------------------------------------
// Final GEMM: out = Y(1024x64) @ U(512x64)^T
// ---------------------------------------------------------------------------
__global__ __launch_bounds__(256) void k_gemm_abt(const float* __restrict__ A,
                                                  const float* __restrict__ B,
                                                  float* __restrict__ C,
                                                  int N, int K) {
    __shared__ float As[32][64];
    __shared__ float Bs[32][64];
    int bm = blockIdx.y * 64, bn = blockIdx.x * 64;
    int tid = threadIdx.x;
    int tx = tid & 15, ty = tid >> 4;
    float acc[4][4] = {};
    for (int kk = 0; kk < K; kk += 32) {
#pragma unroll
        for (int i = 0; i < 2; ++i) {
            int t = tid + i * 256;
            int row = t >> 3;
            int c4 = (t & 7) * 4;
            float4 va = *(const float4*)(A + (size_t)(bm + row) * K + kk + c4);
            As[c4 + 0][row] = va.x; As[c4 + 1][row] = va.y;
            As[c4 + 2][row] = va.z; As[c4 + 3][row] = va.w;
            float4 vb = *(const float4*)(B + (size_t)(bn + row) * K + kk + c4);
            Bs[c4 + 0][row] = vb.x; Bs[c4 + 1][row] = vb.y;
            Bs[c4 + 2][row] = vb.z; Bs[c4 + 3][row] = vb.w;
        }
        __syncthreads();
#pragma unroll 8
        for (int k = 0; k < 32; ++k) {
            float4 a = *(const float4*)&As[k][ty * 4];
            float4 b = *(const float4*)&Bs[k][tx * 4];
            float av[4] = {a.x, a.y, a.z, a.w};
            float bv[4] = {b.x, b.y, b.z, b.w};
#pragma unroll
            for (int i = 0; i < 4; ++i)
#pragma unroll
                for (int j = 0; j < 4; ++j)
                    acc[i][j] = fmaf(av[i], bv[j], acc[i][j]);
        }
        __syncthreads();
    }
#pragma unroll
    for (int i = 0; i < 4; ++i) {
        float4 o = make_float4(acc[i][0], acc[i][1], acc[i][2], acc[i][3]);
        *(float4*)(C + (size_t)(bm + ty * 4 + i) * N + bn + tx * 4) = o;
    }
}

// ---------------------------------------------------------------------------
extern "C" void kernel_launch(void* const* d_in, const int* in_sizes, int n_in,
                              void* d_out, int out_size) {
    const float* x      = (const float*)d_in[0];
    const float* Wq     = (const float*)d_in[1];
    const float* Wk     = (const float*)d_in[2];
    const float* Wv     = (const float*)d_in[3];
    const float* Wo     = (const float*)d_in[4];
    const float* Pin_q  = (const float*)d_in[5];
    const float* Pin_k  = (const float*)d_in[6];
    const float* Pin_v  = (const float*)d_in[7];
    const float* Pout_q = (const float*)d_in[8];
    const float* Pout_k = (const float*)d_in[9];
    const float* Pout_v = (const float*)d_in[10];
    const float* theta  = (const float*)d_in[11];
    float* out = (float*)d_out;

    float *pY, *pU;
    cudaGetSymbolAddress((void**)&pY, g_Y);
    cudaGetSymbolAddress((void**)&pU, g_U);

    // Set unconditionally every call (idempotent host-side call; no static
    // guards allowed by the harness contract).
    int attn_smem = (1024 * 12 + 64 * 12 + 64 + 8) * (int)sizeof(float);
    cudaFuncSetAttribute(k_attn4, cudaFuncAttributeMaxDynamicSharedMemorySize, attn_smem);

    k_fold<<<64, 256>>>(Wq, Wk, Wv, Wo, Pin_q, Pin_k, Pin_v, Pout_v);
    k_gemm_qp<<<dim3(3, 16, 4), 128>>>(x);
    k_attn4<<<dim3(8, 16), 512, attn_smem>>>(Pout_q, Pout_k, theta);
    k_gemm_abt<<<dim3(8, 16), 256>>>(pY, pU, out, 512, 64);
}

// round 7
// speedup vs baseline: 1.0062x; 1.0062x over previous
#include <cuda_runtime.h>
#include <math.h>

#define NTOK 1024   // B*S = 2*512

// Scratch (device globals)
__device__ float g_A[3 * 64 * 512];         // folded Pin@W_head
__device__ float g_U[512 * 64];             // folded Wo@Pout_v
__device__ float g_M[64];                   // Pout_q^T Pout_k / 8
__device__ float g_ct[8];                   // cos(theta_w + theta_{8+w})
__device__ float g_qp_part[4 * NTOK * 192]; // split-K partials of x@A^T
__device__ float g_z[3 * 16 * 512 * 8];     // [stream][bh][s][8]; stream0 folded with M
__device__ float g_Y[NTOK * 64];            // attn out (normalized), [n][h*8+q]

// ---------------------------------------------------------------------------
// Fold kernel. Blocks 0..47: A. Blocks 48..63: U. Block 64: M + ct.
// ---------------------------------------------------------------------------
__global__ __launch_bounds__(256) void k_fold(
    const float* __restrict__ Wq, const float* __restrict__ Wk,
    const float* __restrict__ Wv, const float* __restrict__ Wo,
    const float* __restrict__ Pq, const float* __restrict__ Pk,
    const float* __restrict__ Pv, const float* __restrict__ Poq,
    const float* __restrict__ Pok, const float* __restrict__ Pov,
    const float* __restrict__ theta) {
    __shared__ float sP[512];
    int blk = blockIdx.x;
    int t = threadIdx.x;
    if (blk < 48) {
        int idx = blk * 256 + t;
        int stream = idx >> 12;
        int rem = idx & 4095;
        int h = rem >> 9;
        int e = rem & 511;
        const float* W = (stream == 0) ? Wq : ((stream == 1) ? Wk : Wv);
        const float* P = (stream == 0) ? Pq : ((stream == 1) ? Pk : Pv);
        sP[t] = P[t];
        sP[t + 256] = P[t + 256];
        __syncthreads();
        float acc[8] = {};
#pragma unroll
        for (int d = 0; d < 64; ++d) {
            float w = W[(h * 64 + d) * 512 + e];
#pragma unroll
            for (int q = 0; q < 8; ++q)
                acc[q] = fmaf(sP[q * 64 + d], w, acc[q]);
        }
#pragma unroll
        for (int q = 0; q < 8; ++q)
            g_A[(stream * 64 + h * 8 + q) * 512 + e] = acc[q];
    } else if (blk < 64) {
        int idx = (blk - 48) * 256 + t;
        sP[t] = Pov[t];
        sP[t + 256] = Pov[t + 256];
        __syncthreads();
        int e = idx >> 3, h = idx & 7;
        float acc[8] = {};
#pragma unroll
        for (int d = 0; d < 64; ++d) {
            float w = Wo[e * 512 + h * 64 + d];
#pragma unroll
            for (int q = 0; q < 8; ++q)
                acc[q] = fmaf(w, sP[d * 8 + q], acc[q]);
        }
#pragma unroll
        for (int q = 0; q < 8; ++q)
            g_U[e * 64 + h * 8 + q] = acc[q];
    } else {
        if (t < 64) {
            int i = t >> 3, j = t & 7;
            float acc = 0.f;
#pragma unroll
            for (int d = 0; d < 64; ++d)
                acc = fmaf(Poq[d * 8 + i], Pok[d * 8 + j], acc);
            g_M[t] = acc * 0.125f;
        } else if (t < 72) {
            int w = t - 64;
            g_ct[w] = cosf(theta[w] + theta[8 + w]);
        }
    }
}

// ---------------------------------------------------------------------------
// Split-K GEMM: qp_part[z] = x[:, z*128:(z+1)*128] @ A[:, same]^T
// grid (3, 16, 4), 128 threads, 64x64 tile, BK=32, 8x4 microtile (FMA-bound)
// ---------------------------------------------------------------------------
__global__ __launch_bounds__(128) void k_gemm_qp(const float* __restrict__ A) {
    const float* B = g_A;
    __shared__ float As[32][64];
    __shared__ float Bs[32][64];
    int bm = blockIdx.y * 64, bn = blockIdx.x * 64;
    int z = blockIdx.z;
    float* C = g_qp_part + z * (NTOK * 192);
    int tid = threadIdx.x;
    int tx = tid & 15;
    int ty = tid >> 4;
    float acc[8][4] = {};
    for (int kk = z * 128; kk < z * 128 + 128; kk += 32) {
#pragma unroll
        for (int i = 0; i < 4; ++i) {
            int t = tid + i * 128;
            int row = t >> 3;
            int c4 = (t & 7) * 4;
            float4 va = *(const float4*)(A + (size_t)(bm + row) * 512 + kk + c4);
            As[c4 + 0][row] = va.x; As[c4 + 1][row] = va.y;
            As[c4 + 2][row] = va.z; As[c4 + 3][row] = va.w;
            float4 vb = *(const float4*)(B + (size_t)(bn + row) * 512 + kk + c4);
            Bs[c4 + 0][row] = vb.x; Bs[c4 + 1][row] = vb.y;
            Bs[c4 + 2][row] = vb.z; Bs[c4 + 3][row] = vb.w;
        }
        __syncthreads();
#pragma unroll 8
        for (int k = 0; k < 32; ++k) {
            float4 a0 = *(const float4*)&As[k][ty * 8];
            float4 a1 = *(const float4*)&As[k][ty * 8 + 4];
            float4 b = *(const float4*)&Bs[k][tx * 4];
            float av[8] = {a0.x, a0.y, a0.z, a0.w, a1.x, a1.y, a1.z, a1.w};
            float bv[4] = {b.x, b.y, b.z, b.w};
#pragma unroll
            for (int i = 0; i < 8; ++i)
#pragma unroll
                for (int j = 0; j < 4; ++j)
                    acc[i][j] = fmaf(av[i], bv[j], acc[i][j]);
        }
        __syncthreads();
    }
#pragma unroll
    for (int i = 0; i < 8; ++i) {
        float4 o = make_float4(acc[i][0], acc[i][1], acc[i][2], acc[i][3]);
        *(float4*)(C + (size_t)(bm + ty * 8 + i) * 192 + bn + tx * 4) = o;
    }
}

// ---------------------------------------------------------------------------
// z kernel: sum split-K partials (float4, MLP=8), cos prefix products,
// apply M to q-stream. grid 192 x 128 (one thread per (token, stream, head)).
// ---------------------------------------------------------------------------
__global__ __launch_bounds__(128) void k_z() {
    __shared__ float sM[64];
    __shared__ float sct[8];
    int t = threadIdx.x;
    if (t < 64) sM[t] = g_M[t];
    else if (t < 72) sct[t - 64] = g_ct[t - 64];
    __syncthreads();

    int idx = blockIdx.x * 128 + t;
    int n = idx / 24;
    int slot = idx - n * 24;
    int stream = slot >> 3;
    int h = slot & 7;
    int base = n * 192 + stream * 64 + h * 8;

    float4 a0 = *(const float4*)(g_qp_part + base);
    float4 a1 = *(const float4*)(g_qp_part + base + 4);
    float4 b0 = *(const float4*)(g_qp_part + NTOK * 192 + base);
    float4 b1 = *(const float4*)(g_qp_part + NTOK * 192 + base + 4);
    float4 c0 = *(const float4*)(g_qp_part + 2 * NTOK * 192 + base);
    float4 c1 = *(const float4*)(g_qp_part + 2 * NTOK * 192 + base + 4);
    float4 d0 = *(const float4*)(g_qp_part + 3 * NTOK * 192 + base);
    float4 d1 = *(const float4*)(g_qp_part + 3 * NTOK * 192 + base + 4);
    float ang[8];
    ang[0] = a0.x + b0.x + c0.x + d0.x;
    ang[1] = a0.y + b0.y + c0.y + d0.y;
    ang[2] = a0.z + b0.z + c0.z + d0.z;
    ang[3] = a0.w + b0.w + c0.w + d0.w;
    ang[4] = a1.x + b1.x + c1.x + d1.x;
    ang[5] = a1.y + b1.y + c1.y + d1.y;
    ang[6] = a1.z + b1.z + c1.z + d1.z;
    ang[7] = a1.w + b1.w + c1.w + d1.w;

    float z[8];
    float p = 1.f;
#pragma unroll
    for (int w = 0; w < 8; ++w) {
        p *= cosf(ang[w]) * sct[w];
        z[w] = p;
    }
    float y[8];
    if (stream == 0) {
#pragma unroll
        for (int j = 0; j < 8; ++j) {
            float acc = 0.f;
#pragma unroll
            for (int i = 0; i < 8; ++i)
                acc = fmaf(z[i], sM[i * 8 + j], acc);
            y[j] = acc;
        }
    } else {
#pragma unroll
        for (int j = 0; j < 8; ++j) y[j] = z[j];
    }
    int b = n >> 9, s = n & 511;
    float* dst = g_z + ((size_t)(stream * 16 + b * 8 + h) * 512 + s) * 8;
    *(float4*)dst = make_float4(y[0], y[1], y[2], y[3]);
    *(float4*)(dst + 4) = make_float4(y[4], y[5], y[6], y[7]);
}

// ---------------------------------------------------------------------------
// Rank-8 attention, single pass (scores provably bounded, no max needed).
// grid (16 qtiles of 32 rows, 16 bh), 256 threads = (row 0..31, sub 0..7).
// smem rows stride 12 -> LDS.128, conflict-free. 2 CTAs/SM.
// ---------------------------------------------------------------------------
__global__ __launch_bounds__(256) void k_attn5() {
    extern __shared__ float sm[];
    float* s_zk = sm;              // 512*12
    float* s_zv = sm + 512 * 12;   // 512*12
    int bh = blockIdx.y;
    int b = bh >> 3, h = bh & 7;
    int q0 = blockIdx.x * 32;
    const float* gzq = g_z + (size_t)bh * 4096;
    const float* gzk = g_z + (size_t)(16 + bh) * 4096;
    const float* gzv = g_z + (size_t)(32 + bh) * 4096;
    int tid = threadIdx.x;

    for (int r = tid; r < 512; r += 256) {
        float4 a = ((const float4*)gzk)[r * 2], c = ((const float4*)gzk)[r * 2 + 1];
        *(float4*)(s_zk + r * 12) = a;
        *(float4*)(s_zk + r * 12 + 4) = c;
        float4 e = ((const float4*)gzv)[r * 2], f = ((const float4*)gzv)[r * 2 + 1];
        *(float4*)(s_zv + r * 12) = e;
        *(float4*)(s_zv + r * 12 + 4) = f;
    }
    __syncthreads();

    int row = tid >> 3, sub = tid & 7;
    float y[8];
    {
        float4 a = ((const float4*)gzq)[(q0 + row) * 2];
        float4 bq = ((const float4*)gzq)[(q0 + row) * 2 + 1];
        y[0] = a.x; y[1] = a.y; y[2] = a.z; y[3] = a.w;
        y[4] = bq.x; y[5] = bq.y; y[6] = bq.z; y[7] = bq.w;
    }
    float l = 0.f;
    float acc[8] = {};
#pragma unroll 4
    for (int it = 0; it < 64; ++it) {
        int key = sub + it * 8;
        float4 k0 = *(const float4*)(s_zk + key * 12);
        float4 k1 = *(const float4*)(s_zk + key * 12 + 4);
        float s = y[0] * k0.x;
        s = fmaf(y[1], k0.y, s);
        s = fmaf(y[2], k0.z, s);
        s = fmaf(y[3], k0.w, s);
        s = fmaf(y[4], k1.x, s);
        s = fmaf(y[5], k1.y, s);
        s = fmaf(y[6], k1.z, s);
        s = fmaf(y[7], k1.w, s);
        float p = __expf(s);
        l += p;
        float4 v0 = *(const float4*)(s_zv + key * 12);
        float4 v1 = *(const float4*)(s_zv + key * 12 + 4);
        acc[0] = fmaf(p, v0.x, acc[0]);
        acc[1] = fmaf(p, v0.y, acc[1]);
        acc[2] = fmaf(p, v0.z, acc[2]);
        acc[3] = fmaf(p, v0.w, acc[3]);
        acc[4] = fmaf(p, v1.x, acc[4]);
        acc[5] = fmaf(p, v1.y, acc[5]);
        acc[6] = fmaf(p, v1.z, acc[6]);
        acc[7] = fmaf(p, v1.w, acc[7]);
    }
#pragma unroll
    for (int d = 1; d <= 4; d <<= 1) {
        l += __shfl_xor_sync(0xffffffffu, l, d);
#pragma unroll
        for (int j = 0; j < 8; ++j)
            acc[j] += __shfl_xor_sync(0xffffffffu, acc[j], d);
    }
    if (sub == 0) {
        float inv = 1.f / l;
        int n0 = b * 512 + q0 + row;
        float4* o = (float4*)(g_Y + (size_t)n0 * 64 + h * 8);
        o[0] = make_float4(acc[0] * inv, acc[1] * inv, acc[2] * inv, acc[3] * inv);
        o[1] = make_float4(acc[4] * inv, acc[5] * inv, acc[6] * inv, acc[7] * inv);
    }
}

// ---------------------------------------------------------------------------
// Final GEMM: out = Y(1024x64) @ U(512x64)^T. Tile 32(M)x64(N), BK=64 (one
// sync), grid (8, 32) = 256 blocks, 256 threads, 2x4 microtile.
// ---------------------------------------------------------------------------
__global__ __launch_bounds__(256) void k_gemm_fin(const float* __restrict__ Y,
                                                  const float* __restrict__ U,
                                                  float* __restrict__ C) {
    __shared__ float As[64][32];   // [k][m]
    __shared__ float Bs[64][64];   // [k][n]
    int bm = blockIdx.y * 32, bn = blockIdx.x * 64;
    int tid = threadIdx.x;
    int tx = tid & 15, ty = tid >> 4;   // 16 cols x 16 rows -> 2x4 microtile

    // Load A tile: 32 rows x 64 k = 2048 floats, 8 per thread (2 float4)
#pragma unroll
    for (int i = 0; i < 2; ++i) {
        int t = tid + i * 256;          // 0..511
        int row = t >> 4;               // 0..31
        int c4 = (t & 15) * 4;          // 0..60
        float4 v = *(const float4*)(Y + (size_t)(bm + row) * 64 + c4);
        As[c4 + 0][row] = v.x; As[c4 + 1][row] = v.y;
        As[c4 + 2][row] = v.z; As[c4 + 3][row] = v.w;
    }
    // Load B tile: 64 rows x 64 k = 4096 floats, 16 per thread (4 float4)
#pragma unroll
    for (int i = 0; i < 4; ++i) {
        int t = tid + i * 256;          // 0..1023
        int row = t >> 4;               // 0..63
        int c4 = (t & 15) * 4;
        float4 v = *(const float4*)(U + (size_t)(bn + row) * 64 + c4);
        Bs[c4 + 0][row] = v.x; Bs[c4 + 1][row] = v.y;
        Bs[c4 + 2][row] = v.z; Bs[c4 + 3][row] = v.w;
    }
    __syncthreads();

    float acc[2][4] = {};
#pragma unroll 8
    for (int k = 0; k < 64; ++k) {
        float a0 = As[k][ty * 2];
        float a1 = As[k][ty * 2 + 1];
        float4 bv = *(const float4*)&Bs[k][tx * 4];
        acc[0][0] = fmaf(a0, bv.x, acc[0][0]);
        acc[0][1] = fmaf(a0, bv.y, acc[0][1]);
        acc[0][2] = fmaf(a0, bv.z, acc[0][2]);
        acc[0][3] = fmaf(a0, bv.w, acc[0][3]);
        acc[1][0] = fmaf(a1, bv.x, acc[1][0]);
        acc[1][1] = fmaf(a1, bv.y, acc[1][1]);
        acc[1][2] = fmaf(a1, bv.z, acc[1][2]);
        acc[1][3] = fmaf(a1, bv.w, acc[1][3]);
    }
#pragma unroll
    for (int i = 0; i < 2; ++i) {
        float4 o = make_float4(acc[i][0], acc[i][1], acc[i][2], acc[i][3]);
        *(float4*)(C + (size_t)(bm + ty * 2 + i) * 512 + bn + tx * 4) = o;
    }
}

// ---------------------------------------------------------------------------
extern "C" void kernel_launch(void* const* d_in, const int* in_sizes, int n_in,
                              void* d_out, int out_size) {
    const float* x      = (const float*)d_in[0];
    const float* Wq     = (const float*)d_in[1];
    const float* Wk     = (const float*)d_in[2];
    const float* Wv     = (const float*)d_in[3];
    const float* Wo     = (const float*)d_in[4];
    const float* Pin_q  = (const float*)d_in[5];
    const float* Pin_k  = (const float*)d_in[6];
    const float* Pin_v  = (const float*)d_in[7];
    const float* Pout_q = (const float*)d_in[8];
    const float* Pout_k = (const float*)d_in[9];
    const float* Pout_v = (const float*)d_in[10];
    const float* theta  = (const float*)d_in[11];
    float* out = (float*)d_out;

    float *pY, *pU;
    cudaGetSymbolAddress((void**)&pY, g_Y);
    cudaGetSymbolAddress((void**)&pU, g_U);

    int attn_smem = 1024 * 12 * (int)sizeof(float);  // 48KB
    cudaFuncSetAttribute(k_attn5, cudaFuncAttributeMaxDynamicSharedMemorySize, attn_smem);

    k_fold<<<65, 256>>>(Wq, Wk, Wv, Wo, Pin_q, Pin_k, Pin_v,
                        Pout_q, Pout_k, Pout_v, theta);
    k_gemm_qp<<<dim3(3, 16, 4), 128>>>(x);
    k_z<<<192, 128>>>();
    k_attn5<<<dim3(16, 16), 256, attn_smem>>>();
    k_gemm_fin<<<dim3(8, 32), 256>>>(pY, pU, out);
}

// round 8
// speedup vs baseline: 1.0488x; 1.0423x over previous
#include <cuda_runtime.h>
#include <math.h>

#define NTOK 1024   // B*S = 2*512

// Scratch (device globals)
__device__ float g_A[3 * 64 * 512];         // folded Pin@W_head
__device__ float g_U[512 * 64];             // folded Wo@Pout_v
__device__ float g_M[64];                   // Pout_q^T Pout_k / 8
__device__ float g_ct[8];                   // cos(theta_w + theta_{8+w})
__device__ float g_qp_part[4 * NTOK * 192]; // split-K partials of x@A^T
__device__ float g_z[3 * 16 * 512 * 8];     // [stream][bh][s][8]; stream0 folded with M
__device__ float g_Y[NTOK * 64];            // attn out (normalized), [n][h*8+q]

// ---------------------------------------------------------------------------
// Fold kernel. Blocks 0..47: A. Blocks 48..63: U. Block 64: M + ct.
// ---------------------------------------------------------------------------
__global__ __launch_bounds__(256) void k_fold(
    const float* __restrict__ Wq, const float* __restrict__ Wk,
    const float* __restrict__ Wv, const float* __restrict__ Wo,
    const float* __restrict__ Pq, const float* __restrict__ Pk,
    const float* __restrict__ Pv, const float* __restrict__ Poq,
    const float* __restrict__ Pok, const float* __restrict__ Pov,
    const float* __restrict__ theta) {
    __shared__ float sP[512];
    int blk = blockIdx.x;
    int t = threadIdx.x;
    if (blk < 48) {
        int idx = blk * 256 + t;
        int stream = idx >> 12;
        int rem = idx & 4095;
        int h = rem >> 9;
        int e = rem & 511;
        const float* W = (stream == 0) ? Wq : ((stream == 1) ? Wk : Wv);
        const float* P = (stream == 0) ? Pq : ((stream == 1) ? Pk : Pv);
        sP[t] = P[t];
        sP[t + 256] = P[t + 256];
        __syncthreads();
        float acc[8] = {};
#pragma unroll
        for (int d = 0; d < 64; ++d) {
            float w = W[(h * 64 + d) * 512 + e];
#pragma unroll
            for (int q = 0; q < 8; ++q)
                acc[q] = fmaf(sP[q * 64 + d], w, acc[q]);
        }
#pragma unroll
        for (int q = 0; q < 8; ++q)
            g_A[(stream * 64 + h * 8 + q) * 512 + e] = acc[q];
    } else if (blk < 64) {
        int idx = (blk - 48) * 256 + t;
        sP[t] = Pov[t];
        sP[t + 256] = Pov[t + 256];
        __syncthreads();
        int e = idx >> 3, h = idx & 7;
        float acc[8] = {};
#pragma unroll
        for (int d = 0; d < 64; ++d) {
            float w = Wo[e * 512 + h * 64 + d];
#pragma unroll
            for (int q = 0; q < 8; ++q)
                acc[q] = fmaf(w, sP[d * 8 + q], acc[q]);
        }
#pragma unroll
        for (int q = 0; q < 8; ++q)
            g_U[e * 64 + h * 8 + q] = acc[q];
    } else {
        if (t < 64) {
            int i = t >> 3, j = t & 7;
            float acc = 0.f;
#pragma unroll
            for (int d = 0; d < 64; ++d)
                acc = fmaf(Poq[d * 8 + i], Pok[d * 8 + j], acc);
            g_M[t] = acc * 0.125f;
        } else if (t < 72) {
            int w = t - 64;
            g_ct[w] = cosf(theta[w] + theta[8 + w]);
        }
    }
}

// ---------------------------------------------------------------------------
// Split-K GEMM (R3-proven 256-thread version):
// qp_part[z] = x[:, z*128:(z+1)*128] @ A[:, same]^T
// grid (3, 16, 4), 256 threads, 64x64 tile, BK=32, 4x4 microtile
// ---------------------------------------------------------------------------
__global__ __launch_bounds__(256) void k_gemm_qp(const float* __restrict__ A) {
    const float* B = g_A;
    __shared__ float As[32][64];
    __shared__ float Bs[32][64];
    int bm = blockIdx.y * 64, bn = blockIdx.x * 64;
    int z = blockIdx.z;
    float* C = g_qp_part + z * (NTOK * 192);
    int tid = threadIdx.x, tx = tid & 15, ty = tid >> 4;
    float acc[4][4] = {};
    for (int kk = z * 128; kk < z * 128 + 128; kk += 32) {
#pragma unroll
        for (int i = 0; i < 2; ++i) {
            int t = tid + i * 256;
            int row = t >> 3;
            int c4 = (t & 7) * 4;
            float4 va = *(const float4*)(A + (size_t)(bm + row) * 512 + kk + c4);
            As[c4 + 0][row] = va.x; As[c4 + 1][row] = va.y;
            As[c4 + 2][row] = va.z; As[c4 + 3][row] = va.w;
            float4 vb = *(const float4*)(B + (size_t)(bn + row) * 512 + kk + c4);
            Bs[c4 + 0][row] = vb.x; Bs[c4 + 1][row] = vb.y;
            Bs[c4 + 2][row] = vb.z; Bs[c4 + 3][row] = vb.w;
        }
        __syncthreads();
#pragma unroll 8
        for (int k = 0; k < 32; ++k) {
            float4 a = *(const float4*)&As[k][ty * 4];
            float4 b = *(const float4*)&Bs[k][tx * 4];
            float av[4] = {a.x, a.y, a.z, a.w};
            float bv[4] = {b.x, b.y, b.z, b.w};
#pragma unroll
            for (int i = 0; i < 4; ++i)
#pragma unroll
                for (int j = 0; j < 4; ++j)
                    acc[i][j] = fmaf(av[i], bv[j], acc[i][j]);
        }
        __syncthreads();
    }
#pragma unroll
    for (int i = 0; i < 4; ++i) {
        float4 o = make_float4(acc[i][0], acc[i][1], acc[i][2], acc[i][3]);
        *(float4*)(C + (size_t)(bm + ty * 4 + i) * 192 + bn + tx * 4) = o;
    }
}

// ---------------------------------------------------------------------------
// z kernel: sum split-K partials (float4, MLP=8), cos prefix products,
// apply M to q-stream. grid 192 x 128.
// ---------------------------------------------------------------------------
__global__ __launch_bounds__(128) void k_z() {
    __shared__ float sM[64];
    __shared__ float sct[8];
    int t = threadIdx.x;
    if (t < 64) sM[t] = g_M[t];
    else if (t < 72) sct[t - 64] = g_ct[t - 64];
    __syncthreads();

    int idx = blockIdx.x * 128 + t;
    int n = idx / 24;
    int slot = idx - n * 24;
    int stream = slot >> 3;
    int h = slot & 7;
    int base = n * 192 + stream * 64 + h * 8;

    float4 a0 = *(const float4*)(g_qp_part + base);
    float4 a1 = *(const float4*)(g_qp_part + base + 4);
    float4 b0 = *(const float4*)(g_qp_part + NTOK * 192 + base);
    float4 b1 = *(const float4*)(g_qp_part + NTOK * 192 + base + 4);
    float4 c0 = *(const float4*)(g_qp_part + 2 * NTOK * 192 + base);
    float4 c1 = *(const float4*)(g_qp_part + 2 * NTOK * 192 + base + 4);
    float4 d0 = *(const float4*)(g_qp_part + 3 * NTOK * 192 + base);
    float4 d1 = *(const float4*)(g_qp_part + 3 * NTOK * 192 + base + 4);
    float ang[8];
    ang[0] = a0.x + b0.x + c0.x + d0.x;
    ang[1] = a0.y + b0.y + c0.y + d0.y;
    ang[2] = a0.z + b0.z + c0.z + d0.z;
    ang[3] = a0.w + b0.w + c0.w + d0.w;
    ang[4] = a1.x + b1.x + c1.x + d1.x;
    ang[5] = a1.y + b1.y + c1.y + d1.y;
    ang[6] = a1.z + b1.z + c1.z + d1.z;
    ang[7] = a1.w + b1.w + c1.w + d1.w;

    float z[8];
    float p = 1.f;
#pragma unroll
    for (int w = 0; w < 8; ++w) {
        p *= cosf(ang[w]) * sct[w];
        z[w] = p;
    }
    float y[8];
    if (stream == 0) {
#pragma unroll
        for (int j = 0; j < 8; ++j) {
            float acc = 0.f;
#pragma unroll
            for (int i = 0; i < 8; ++i)
                acc = fmaf(z[i], sM[i * 8 + j], acc);
            y[j] = acc;
        }
    } else {
#pragma unroll
        for (int j = 0; j < 8; ++j) y[j] = z[j];
    }
    int b = n >> 9, s = n & 511;
    float* dst = g_z + ((size_t)(stream * 16 + b * 8 + h) * 512 + s) * 8;
    *(float4*)dst = make_float4(y[0], y[1], y[2], y[3]);
    *(float4*)(dst + 4) = make_float4(y[4], y[5], y[6], y[7]);
}

// ---------------------------------------------------------------------------
// Rank-8 attention v6: R=4 rows/thread (k/v LDS amortized 4x) AND 256 blocks.
// grid (16 qtiles of 32 rows, 16 bh), 128 threads = (rowgroup 0..7 of 4 rows,
// sub 0..15 handling 32 keys each). Single-pass softmax (scores bounded).
// smem rows stride 12 -> LDS.128 conflict-free. 4-warp blocks stack 3-4/SM.
// ---------------------------------------------------------------------------
__global__ __launch_bounds__(128) void k_attn6() {
    extern __shared__ float sm[];
    float* s_zk = sm;              // 512*12
    float* s_zv = sm + 512 * 12;   // 512*12
    int bh = blockIdx.y;
    int b = bh >> 3, h = bh & 7;
    int q0 = blockIdx.x * 32;
    const float* gzq = g_z + (size_t)bh * 4096;
    const float* gzk = g_z + (size_t)(16 + bh) * 4096;
    const float* gzv = g_z + (size_t)(32 + bh) * 4096;
    int tid = threadIdx.x;

    for (int r = tid; r < 512; r += 128) {
        float4 a = ((const float4*)gzk)[r * 2], c = ((const float4*)gzk)[r * 2 + 1];
        *(float4*)(s_zk + r * 12) = a;
        *(float4*)(s_zk + r * 12 + 4) = c;
        float4 e = ((const float4*)gzv)[r * 2], f = ((const float4*)gzv)[r * 2 + 1];
        *(float4*)(s_zv + r * 12) = e;
        *(float4*)(s_zv + r * 12 + 4) = f;
    }
    __syncthreads();

    int rg = tid >> 4, sub = tid & 15;
    int r0 = q0 + rg * 4;
    float y[4][8];
#pragma unroll
    for (int r = 0; r < 4; ++r) {
        float4 a = ((const float4*)gzq)[(r0 + r) * 2];
        float4 bq = ((const float4*)gzq)[(r0 + r) * 2 + 1];
        y[r][0] = a.x; y[r][1] = a.y; y[r][2] = a.z; y[r][3] = a.w;
        y[r][4] = bq.x; y[r][5] = bq.y; y[r][6] = bq.z; y[r][7] = bq.w;
    }

    float l[4] = {};
    float acc[4][8] = {};
#pragma unroll 4
    for (int it = 0; it < 32; ++it) {
        int key = sub + it * 16;
        float4 k0 = *(const float4*)(s_zk + key * 12);
        float4 k1 = *(const float4*)(s_zk + key * 12 + 4);
        float kr[8] = {k0.x, k0.y, k0.z, k0.w, k1.x, k1.y, k1.z, k1.w};
        float p[4];
#pragma unroll
        for (int r = 0; r < 4; ++r) {
            float s = y[r][0] * kr[0];
#pragma unroll
            for (int j = 1; j < 8; ++j) s = fmaf(y[r][j], kr[j], s);
            p[r] = __expf(s);
            l[r] += p[r];
        }
        float4 v0 = *(const float4*)(s_zv + key * 12);
        float4 v1 = *(const float4*)(s_zv + key * 12 + 4);
        float vr[8] = {v0.x, v0.y, v0.z, v0.w, v1.x, v1.y, v1.z, v1.w};
#pragma unroll
        for (int r = 0; r < 4; ++r)
#pragma unroll
            for (int j = 0; j < 8; ++j)
                acc[r][j] = fmaf(p[r], vr[j], acc[r][j]);
    }

    // reduce over 16 subs (lanes 0..15 / 16..31 independent rowgroups)
#pragma unroll
    for (int d = 1; d <= 8; d <<= 1) {
#pragma unroll
        for (int r = 0; r < 4; ++r) {
            l[r] += __shfl_xor_sync(0xffffffffu, l[r], d);
#pragma unroll
            for (int j = 0; j < 8; ++j)
                acc[r][j] += __shfl_xor_sync(0xffffffffu, acc[r][j], d);
        }
    }
    if (sub == 0) {
#pragma unroll
        for (int r = 0; r < 4; ++r) {
            float inv = 1.f / l[r];
            int n0 = b * 512 + r0 + r;
            float4* o = (float4*)(g_Y + (size_t)n0 * 64 + h * 8);
            o[0] = make_float4(acc[r][0] * inv, acc[r][1] * inv, acc[r][2] * inv, acc[r][3] * inv);
            o[1] = make_float4(acc[r][4] * inv, acc[r][5] * inv, acc[r][6] * inv, acc[r][7] * inv);
        }
    }
}

// ---------------------------------------------------------------------------
// Final GEMM: out = Y(1024x64) @ U(512x64)^T. Tile 32(M)x64(N), BK=64 (one
// sync), grid (8, 32) = 256 blocks, 256 threads, 2x4 microtile.
// ---------------------------------------------------------------------------
__global__ __launch_bounds__(256) void k_gemm_fin(const float* __restrict__ Y,
                                                  const float* __restrict__ U,
                                                  float* __restrict__ C) {
    __shared__ float As[64][32];   // [k][m]
    __shared__ float Bs[64][64];   // [k][n]
    int bm = blockIdx.y * 32, bn = blockIdx.x * 64;
    int tid = threadIdx.x;
    int tx = tid & 15, ty = tid >> 4;

#pragma unroll
    for (int i = 0; i < 2; ++i) {
        int t = tid + i * 256;
        int row = t >> 4;
        int c4 = (t & 15) * 4;
        float4 v = *(const float4*)(Y + (size_t)(bm + row) * 64 + c4);
        As[c4 + 0][row] = v.x; As[c4 + 1][row] = v.y;
        As[c4 + 2][row] = v.z; As[c4 + 3][row] = v.w;
    }
#pragma unroll
    for (int i = 0; i < 4; ++i) {
        int t = tid + i * 256;
        int row = t >> 4;
        int c4 = (t & 15) * 4;
        float4 v = *(const float4*)(U + (size_t)(bn + row) * 64 + c4);
        Bs[c4 + 0][row] = v.x; Bs[c4 + 1][row] = v.y;
        Bs[c4 + 2][row] = v.z; Bs[c4 + 3][row] = v.w;
    }
    __syncthreads();

    float acc[2][4] = {};
#pragma unroll 8
    for (int k = 0; k < 64; ++k) {
        float a0 = As[k][ty * 2];
        float a1 = As[k][ty * 2 + 1];
        float4 bv = *(const float4*)&Bs[k][tx * 4];
        acc[0][0] = fmaf(a0, bv.x, acc[0][0]);
        acc[0][1] = fmaf(a0, bv.y, acc[0][1]);
        acc[0][2] = fmaf(a0, bv.z, acc[0][2]);
        acc[0][3] = fmaf(a0, bv.w, acc[0][3]);
        acc[1][0] = fmaf(a1, bv.x, acc[1][0]);
        acc[1][1] = fmaf(a1, bv.y, acc[1][1]);
        acc[1][2] = fmaf(a1, bv.z, acc[1][2]);
        acc[1][3] = fmaf(a1, bv.w, acc[1][3]);
    }
#pragma unroll
    for (int i = 0; i < 2; ++i) {
        float4 o = make_float4(acc[i][0], acc[i][1], acc[i][2], acc[i][3]);
        *(float4*)(C + (size_t)(bm + ty * 2 + i) * 512 + bn + tx * 4) = o;
    }
}

// ---------------------------------------------------------------------------
extern "C" void kernel_launch(void* const* d_in, const int* in_sizes, int n_in,
                              void* d_out, int out_size) {
    const float* x      = (const float*)d_in[0];
    const float* Wq     = (const float*)d_in[1];
    const float* Wk     = (const float*)d_in[2];
    const float* Wv     = (const float*)d_in[3];
    const float* Wo     = (const float*)d_in[4];
    const float* Pin_q  = (const float*)d_in[5];
    const float* Pin_k  = (const float*)d_in[6];
    const float* Pin_v  = (const float*)d_in[7];
    const float* Pout_q = (const float*)d_in[8];
    const float* Pout_k = (const float*)d_in[9];
    const float* Pout_v = (const float*)d_in[10];
    const float* theta  = (const float*)d_in[11];
    float* out = (float*)d_out;

    float *pY, *pU;
    cudaGetSymbolAddress((void**)&pY, g_Y);
    cudaGetSymbolAddress((void**)&pU, g_U);

    int attn_smem = 1024 * 12 * (int)sizeof(float);  // 48KB
    cudaFuncSetAttribute(k_attn6, cudaFuncAttributeMaxDynamicSharedMemorySize, attn_smem);

    k_fold<<<65, 256>>>(Wq, Wk, Wv, Wo, Pin_q, Pin_k, Pin_v,
                        Pout_q, Pout_k, Pout_v, theta);
    k_gemm_qp<<<dim3(3, 16, 4), 256>>>(x);
    k_z<<<192, 128>>>();
    k_attn6<<<dim3(16, 16), 128, attn_smem>>>();
    k_gemm_fin<<<dim3(8, 32), 256>>>(pY, pU, out);
}